// round 1
// baseline (speedup 1.0000x reference)
#include <cuda_runtime.h>

#define AA 512      // attention length
#define OUTS 512    // out_size
#define HH 512
#define WW 512
#define CC 3
#define NMAX 32

// scratch (allocation-free rule: device globals)
__device__ float g_px[NMAX * OUTS];
__device__ float g_py[NMAX * OUTS];

__device__ __forceinline__ float warpSum(float v) {
    #pragma unroll
    for (int o = 16; o; o >>= 1) v += __shfl_xor_sync(0xffffffffu, v, o);
    return v;
}
__device__ __forceinline__ float warpMax(float v) {
    #pragma unroll
    for (int o = 16; o; o >>= 1) v = fmaxf(v, __shfl_xor_sync(0xffffffffu, v, o));
    return v;
}

// block of 512 threads
__device__ float blockSum(float v, volatile float* sbuf) {
    int lane = threadIdx.x & 31, w = threadIdx.x >> 5;
    v = warpSum(v);
    if (lane == 0) sbuf[w] = v;
    __syncthreads();
    if (w == 0) {
        float r = (lane < 16) ? sbuf[lane] : 0.f;
        r = warpSum(r);
        if (lane == 0) sbuf[0] = r;
    }
    __syncthreads();
    float res = sbuf[0];
    __syncthreads();
    return res;
}

__device__ float blockMax(float v, volatile float* sbuf) {
    int lane = threadIdx.x & 31, w = threadIdx.x >> 5;
    v = warpMax(v);
    if (lane == 0) sbuf[w] = v;
    __syncthreads();
    if (w == 0) {
        float r = (lane < 16) ? sbuf[lane] : -3.4e38f;
        r = warpMax(r);
        if (lane == 0) sbuf[0] = r;
    }
    __syncthreads();
    float res = sbuf[0];
    __syncthreads();
    return res;
}

// inclusive block scan of 512 values -> out[tid]
__device__ void blockScan(float v, float* out, volatile float* sbuf) {
    int lane = threadIdx.x & 31, w = threadIdx.x >> 5;
    float s = v;
    #pragma unroll
    for (int o = 1; o < 32; o <<= 1) {
        float t = __shfl_up_sync(0xffffffffu, s, o);
        if (lane >= o) s += t;
    }
    if (lane == 31) sbuf[w] = s;
    __syncthreads();
    if (w == 0 && lane < 16) {
        float ws = sbuf[lane];
        #pragma unroll
        for (int o = 1; o < 16; o <<= 1) {
            float t = __shfl_up_sync(0x0000ffffu, ws, o);
            if (lane >= o) ws += t;
        }
        sbuf[lane] = ws;
    }
    __syncthreads();
    float off = (w > 0) ? sbuf[w - 1] : 0.f;
    out[threadIdx.x] = s + off;
    __syncthreads();
}

__device__ __forceinline__ float inv_cdf_one(const float* c, float tk) {
    // searchsorted left: first j with c[j] >= tk
    int l = 0, h = AA;
    while (l < h) {
        int m = (l + h) >> 1;
        if (c[m] < tk) l = m + 1; else h = m;
    }
    int j = min(l, AA - 1);
    float cp = (j > 0) ? c[j - 1] : 0.f;
    float dens = c[j] - cp;
    float p = (float)j + (tk - cp) / fmaxf(dens, 1e-6f);
    return 2.f * p / (float)AA - 1.f;
}

__global__ void __launch_bounds__(512) prep_kernel(const float* __restrict__ attx,
                                                   const float* __restrict__ atty) {
    __shared__ float sbuf[32];
    __shared__ float cx[AA];
    __shared__ float cy[AA];
    int n = blockIdx.x;
    int t = threadIdx.x;

    float ax = attx[n * AA + t];
    float ay = atty[n * AA + t];

    float sax = blockSum(ax, sbuf);
    float say = blockSum(ay, sbuf);
    ax = ax / sax * (float)OUTS;
    ay = ay / say * (float)OUTS;

    const float thr0 = 4.0f * (float)OUTS / (float)AA;  // DENSE*out/A
    #pragma unroll
    for (int it = 0; it < 5; ++it) {
        float mx = blockMax(ax, sbuf);
        float my = blockMax(ay, sbuf);
        float tt = fminf(mx, my);
        if (it == 0) tt = fminf(tt, thr0);
        ax = fminf(ax, tt);
        ay = fminf(ay, tt);
        sax = blockSum(ax, sbuf);
        say = blockSum(ay, sbuf);
        ax += ((float)OUTS - sax) / (float)AA;
        ay += ((float)OUTS - say) / (float)AA;
    }

    blockScan(ax, cx, sbuf);
    blockScan(ay, cy, sbuf);

    float stepx = cx[AA - 1] / (float)OUTS;
    float stepy = cy[AA - 1] / (float)OUTS;
    float tkx = ((float)t + 0.5f) * stepx;
    float tky = ((float)t + 0.5f) * stepy;

    g_px[n * OUTS + t] = inv_cdf_one(cx, tkx);
    g_py[n * OUTS + t] = inv_cdf_one(cy, tky);
}

__global__ void __launch_bounds__(512) sample_kernel(const float* __restrict__ data,
                                                     float* __restrict__ out_s,
                                                     float2* __restrict__ out_g) {
    int j = threadIdx.x;
    int i = blockIdx.x;
    int n = blockIdx.y;

    float px = __ldg(&g_px[n * OUTS + j]);
    float py = __ldg(&g_py[n * OUTS + i]);

    float ix = (px + 1.f) * 0.5f * (float)(WW - 1);
    float iy = (py + 1.f) * 0.5f * (float)(HH - 1);
    float fx = floorf(ix), fy = floorf(iy);
    float wx = ix - fx, wy = iy - fy;
    int x0 = min(max((int)fx, 0), WW - 1);
    int x1 = min(x0 + 1, WW - 1);
    int y0 = min(max((int)fy, 0), HH - 1);
    int y1 = min(y0 + 1, HH - 1);

    const float* img = data + (size_t)n * CC * HH * WW;
    size_t r0 = (size_t)y0 * WW;
    size_t r1 = (size_t)y1 * WW;

    float* o = out_s + (((size_t)n * CC) * HH + i) * WW + j;
    float omwx = 1.f - wx, omwy = 1.f - wy;

    #pragma unroll
    for (int c = 0; c < CC; ++c) {
        const float* ch = img + (size_t)c * HH * WW;
        float v00 = __ldg(ch + r0 + x0);
        float v01 = __ldg(ch + r0 + x1);
        float v10 = __ldg(ch + r1 + x0);
        float v11 = __ldg(ch + r1 + x1);
        float top = v00 * omwx + v01 * wx;
        float bot = v10 * omwx + v11 * wx;
        o[(size_t)c * HH * WW] = top * omwy + bot * wy;
    }

    out_g[((size_t)n * OUTS + i) * OUTS + j] = make_float2(px, py);
}

extern "C" void kernel_launch(void* const* d_in, const int* in_sizes, int n_in,
                              void* d_out, int out_size) {
    const float* data = (const float*)d_in[0];
    const float* attx = (const float*)d_in[1];
    const float* atty = (const float*)d_in[2];

    int N = in_sizes[1] / AA;   // attx is (N, 512, 1)

    float* out = (float*)d_out;
    float* out_s = out;                                        // (N, C, 512, 512)
    float2* out_g = (float2*)(out + (size_t)N * CC * HH * WW); // (N, 512, 512, 2)

    prep_kernel<<<N, 512>>>(attx, atty);
    dim3 grid(OUTS, N);
    sample_kernel<<<grid, 512>>>(data, out_s, out_g);
}